// round 6
// baseline (speedup 1.0000x reference)
#include <cuda_runtime.h>
#include <cstdint>

// Problem constants (fixed shapes for this problem)
#define NS   1024      // n_states
#define NT   8192      // T (save points); NT-1 = 8191 integration steps
#define NO   256       // n_out
#define NBLK 128       // persistent blocks
#define NTHR 256       // threads per block
#define RPB  8         // rows of A per block = NS / NBLK

// Global scratch (no allocations allowed)
__device__ __align__(16) float g_k[6][NS];
// 8 arrival counters, each in its own 256B region (distinct L2 lines) to
// spread the atomic serialization (128 atomics to 1 addr ~= 3500 cyc; 16 per
// addr across 8 slices ~= 430 cyc).
#define CSTRIDE 64
__device__ unsigned int g_ctr[8 * CSTRIDE];

__global__ void init_kernel() {
    if (threadIdx.x < 8) g_ctr[threadIdx.x * CSTRIDE] = 0u;
}

__device__ __forceinline__ float warp_sum(float v) {
#pragma unroll
    for (int o = 16; o > 0; o >>= 1) v += __shfl_down_sync(0xffffffffu, v, o);
    return v;
}

// ---------------------------------------------------------------------------
// Persistent ODE kernel — EXACT R1 protocol (the only configuration that has
// passed): kcol smem gather; thread0 does publish -> fence -> atomic ->
// volatile spin -> fence, all in one thread; 3 bars/stage. Sole change vs R1:
// the single arrival counter is split into 8 (block b arrives on b&7; spin
// checks all 8 >= 16*stage).
// ---------------------------------------------------------------------------
__global__ void __launch_bounds__(NTHR, 1)
ode_kernel(const float* __restrict__ x0, const float* __restrict__ t,
           const float* __restrict__ A, float* __restrict__ xs)
{
    __shared__ float ty_sm[NS];
    __shared__ __align__(16) float kcol[RPB];

    const int tid = threadIdx.x;
    const int b   = blockIdx.x;
    const int w   = tid >> 5;        // warp id = local row
    const int l   = tid & 31;        // lane
    const int R   = b * RPB + w;     // global row this warp produces
    const int j0  = tid * 4;         // 4 contiguous state indices owned

    const float dt = __ldg(&t[1]) - __ldg(&t[0]);

    // A[R][l + 32*i] -> registers (coalesced per i across lanes)
    float a[32];
#pragma unroll
    for (int i = 0; i < 32; i++) a[i] = __ldg(&A[R * NS + l + 32 * i]);

    float4 xv = *reinterpret_cast<const float4*>(&x0[j0]);
    float xr[4] = {xv.x, xv.y, xv.z, xv.w};
    float k0[4], k1[4], k2[4], k3[4], k4[4], k5[4];

    // xs row 0 = x0, written by the owning block's two threads
    if ((tid >> 1) == b) {
        *reinterpret_cast<float4*>(&xs[j0]) = xv;
    }

    unsigned int t16 = 0;            // per-counter target: 16 per stage
    const int myc = (b & 7) * CSTRIDE;

#define TANH_STORE(Y0, Y1, Y2, Y3) do {                                     \
        float4 tv;                                                          \
        tv.x = tanhf(Y0); tv.y = tanhf(Y1);                                 \
        tv.z = tanhf(Y2); tv.w = tanhf(Y3);                                 \
        *reinterpret_cast<float4*>(&ty_sm[j0]) = tv;                        \
    } while (0)

#define MATVEC_PUBLISH(S) do {                                              \
        __syncthreads();                                                    \
        float acc = 0.0f;                                                   \
        _Pragma("unroll")                                                   \
        for (int i = 0; i < 32; i++)                                        \
            acc = fmaf(a[i], ty_sm[l + 32 * i], acc);                       \
        acc = warp_sum(acc);                                                \
        if (l == 0) kcol[w] = acc;                                          \
        __syncthreads();                                                    \
        t16 += 16;                                                          \
        if (tid == 0) {                                                     \
            float4 v0 = *reinterpret_cast<float4*>(&kcol[0]);               \
            float4 v1 = *reinterpret_cast<float4*>(&kcol[4]);               \
            *reinterpret_cast<float4*>(&g_k[S][b * RPB])     = v0;          \
            *reinterpret_cast<float4*>(&g_k[S][b * RPB + 4]) = v1;          \
            __threadfence();                                                \
            atomicAdd(&g_ctr[myc], 1u);                                     \
            volatile unsigned int* cp = g_ctr;                              \
            bool wait = true;                                               \
            while (wait) {                                                  \
                wait = false;                                               \
                _Pragma("unroll")                                           \
                for (int q = 0; q < 8; q++)                                 \
                    if (cp[q * CSTRIDE] < t16) wait = true;                 \
            }                                                               \
            __threadfence();                                                \
        }                                                                   \
        __syncthreads();                                                    \
    } while (0)

#define LOADK(KR, S) do {                                                   \
        float4 kv = __ldcg(reinterpret_cast<const float4*>(&g_k[S][j0]));   \
        KR[0] = kv.x; KR[1] = kv.y; KR[2] = kv.z; KR[3] = kv.w;             \
    } while (0)

    for (int step = 0; step < NT - 1; step++) {
        // ---- stage 1: y = x ----
        TANH_STORE(xr[0], xr[1], xr[2], xr[3]);
        MATVEC_PUBLISH(0);

        // ---- stage 2: y = x + dt*(1/5 k1) ----
        LOADK(k0, 0);
        {
            float y[4];
#pragma unroll
            for (int e = 0; e < 4; e++) {
                float acc = 0.2f * k0[e];
                y[e] = fmaf(dt, acc, xr[e]);
            }
            TANH_STORE(y[0], y[1], y[2], y[3]);
        }
        MATVEC_PUBLISH(1);

        // ---- stage 3: y = x + dt*(3/40 k1 + 9/40 k2) ----
        LOADK(k1, 1);
        {
            float y[4];
#pragma unroll
            for (int e = 0; e < 4; e++) {
                float acc = (3.0f / 40.0f) * k0[e];
                acc = fmaf(9.0f / 40.0f, k1[e], acc);
                y[e] = fmaf(dt, acc, xr[e]);
            }
            TANH_STORE(y[0], y[1], y[2], y[3]);
        }
        MATVEC_PUBLISH(2);

        // ---- stage 4: y = x + dt*(44/45 k1 - 56/15 k2 + 32/9 k3) ----
        LOADK(k2, 2);
        {
            float y[4];
#pragma unroll
            for (int e = 0; e < 4; e++) {
                float acc = (44.0f / 45.0f) * k0[e];
                acc = fmaf(-56.0f / 15.0f, k1[e], acc);
                acc = fmaf(32.0f / 9.0f,  k2[e], acc);
                y[e] = fmaf(dt, acc, xr[e]);
            }
            TANH_STORE(y[0], y[1], y[2], y[3]);
        }
        MATVEC_PUBLISH(3);

        // ---- stage 5 ----
        LOADK(k3, 3);
        {
            float y[4];
#pragma unroll
            for (int e = 0; e < 4; e++) {
                float acc = (19372.0f / 6561.0f) * k0[e];
                acc = fmaf(-25360.0f / 2187.0f, k1[e], acc);
                acc = fmaf(64448.0f / 6561.0f,  k2[e], acc);
                acc = fmaf(-212.0f / 729.0f,    k3[e], acc);
                y[e] = fmaf(dt, acc, xr[e]);
            }
            TANH_STORE(y[0], y[1], y[2], y[3]);
        }
        MATVEC_PUBLISH(4);

        // ---- stage 6 ----
        LOADK(k4, 4);
        {
            float y[4];
#pragma unroll
            for (int e = 0; e < 4; e++) {
                float acc = (9017.0f / 3168.0f) * k0[e];
                acc = fmaf(-355.0f / 33.0f,     k1[e], acc);
                acc = fmaf(46732.0f / 5247.0f,  k2[e], acc);
                acc = fmaf(49.0f / 176.0f,      k3[e], acc);
                acc = fmaf(-5103.0f / 18656.0f, k4[e], acc);
                y[e] = fmaf(dt, acc, xr[e]);
            }
            TANH_STORE(y[0], y[1], y[2], y[3]);
        }
        MATVEC_PUBLISH(5);

        // ---- step update ----
        LOADK(k5, 5);
#pragma unroll
        for (int e = 0; e < 4; e++) {
            float acc = (35.0f / 384.0f) * k0[e];
            acc = fmaf(500.0f / 1113.0f,   k2[e], acc);
            acc = fmaf(125.0f / 192.0f,    k3[e], acc);
            acc = fmaf(-2187.0f / 6784.0f, k4[e], acc);
            acc = fmaf(11.0f / 84.0f,      k5[e], acc);
            xr[e] = fmaf(dt, acc, xr[e]);
        }
        if ((tid >> 1) == b) {
            float4 o;
            o.x = xr[0]; o.y = xr[1]; o.z = xr[2]; o.w = xr[3];
            *reinterpret_cast<float4*>(&xs[(size_t)(step + 1) * NS + j0]) = o;
        }
    }

#undef TANH_STORE
#undef MATVEC_PUBLISH
#undef LOADK
}

// ---------------------------------------------------------------------------
// ys = xs @ C^T  (8192x1024 @ 1024x256) — 64x64 tiled fp32 GEMM.
// ---------------------------------------------------------------------------
__global__ void __launch_bounds__(256)
gemm_ys(const float* __restrict__ xs, const float* __restrict__ C,
        float* __restrict__ ys)
{
    const int BM = 64, BN = 64, BK = 16;
    __shared__ float As[BK][BM];
    __shared__ float Bs[BK][BN];

    const int tid = threadIdx.x;
    const int m0 = blockIdx.y * BM;
    const int n0 = blockIdx.x * BN;
    const int tx = tid & 15;
    const int ty = tid >> 4;

    const int lr = tid >> 2;
    const int lc = (tid & 3) * 4;

    float acc[4][4];
#pragma unroll
    for (int i = 0; i < 4; i++)
#pragma unroll
        for (int j = 0; j < 4; j++) acc[i][j] = 0.0f;

    for (int kk0 = 0; kk0 < NS; kk0 += BK) {
        float4 av = *reinterpret_cast<const float4*>(
            &xs[(size_t)(m0 + lr) * NS + kk0 + lc]);
        float4 bv = *reinterpret_cast<const float4*>(
            &C[(size_t)(n0 + lr) * NS + kk0 + lc]);
        As[lc + 0][lr] = av.x; As[lc + 1][lr] = av.y;
        As[lc + 2][lr] = av.z; As[lc + 3][lr] = av.w;
        Bs[lc + 0][lr] = bv.x; Bs[lc + 1][lr] = bv.y;
        Bs[lc + 2][lr] = bv.z; Bs[lc + 3][lr] = bv.w;
        __syncthreads();

#pragma unroll
        for (int kk = 0; kk < BK; kk++) {
            float ar[4], br[4];
#pragma unroll
            for (int i = 0; i < 4; i++) ar[i] = As[kk][ty * 4 + i];
#pragma unroll
            for (int j = 0; j < 4; j++) br[j] = Bs[kk][tx * 4 + j];
#pragma unroll
            for (int i = 0; i < 4; i++)
#pragma unroll
                for (int j = 0; j < 4; j++)
                    acc[i][j] = fmaf(ar[i], br[j], acc[i][j]);
        }
        __syncthreads();
    }

#pragma unroll
    for (int i = 0; i < 4; i++)
#pragma unroll
        for (int j = 0; j < 4; j++)
            ys[(size_t)(m0 + ty * 4 + i) * NO + n0 + tx * 4 + j] = acc[i][j];
}

extern "C" void kernel_launch(void* const* d_in, const int* in_sizes, int n_in,
                              void* d_out, int out_size)
{
    const float* x0 = (const float*)d_in[0];
    const float* t  = (const float*)d_in[1];
    const float* A  = (const float*)d_in[2];
    const float* C  = (const float*)d_in[3];
    float* out = (float*)d_out;

    // Reset all 8 arrival counters (graph-replay safe).
    init_kernel<<<1, 32>>>();

    // Persistent ODE integration: writes xs = out[0 : NT*NS]
    ode_kernel<<<NBLK, NTHR>>>(x0, t, A, out);

    // Output projection: ys = out[NT*NS : ]
    dim3 g(NO / 64, NT / 64);
    gemm_ys<<<g, 256>>>(out, C, out + (size_t)NT * NS);
}

// round 10
// speedup vs baseline: 1.0246x; 1.0246x over previous
#include <cuda_runtime.h>
#include <cstdint>

#define NS   1024      // n_states
#define NT   8192      // T; NT-1 = 8191 steps
#define NO   256       // n_out
#define NBLK 128       // persistent blocks
#define NTHR 256       // threads per block
#define RPB  8         // rows per block

// k-value buffers (6 rotating stages) + per-block release/acquire flags.
__device__ __align__(16) float g_k[6][NS];
#define FSTRIDE 32                      // 128B apart -> distinct L2 lines
__device__ unsigned int g_flag[NBLK * FSTRIDE];

__global__ void init_kernel() {
    int i = blockIdx.x * blockDim.x + threadIdx.x;   // 16*256 = 4096
    g_flag[i] = 0u;
}

// Acquire-spin until producer flag >= sc (strong gpu-scope op: L2-serviced,
// cannot read stale L1; acquire orders the subsequent __ldcg value loads).
__device__ __forceinline__ void wait_flag(const unsigned int* f, unsigned sc) {
    unsigned v;
    do {
        asm volatile("ld.acquire.gpu.global.u32 %0, [%1];"
                     : "=r"(v) : "l"(f) : "memory");
    } while (v < sc);
}

__global__ void __launch_bounds__(NTHR, 1)
ode_kernel(const float* __restrict__ x0, const float* __restrict__ t,
           const float* __restrict__ A, float* __restrict__ xs)
{
    __shared__ float ty_sm[NS];
    __shared__ __align__(16) float kcol[RPB];

    const int tid = threadIdx.x;
    const int b   = blockIdx.x;
    const int w   = tid >> 5;        // warp = local row
    const int l   = tid & 31;
    const int R   = b * RPB + w;     // global row this warp produces
    const int j0  = tid * 4;         // 4 owned state indices (rows 4t..4t+3)

    // Producer block of this thread's 4 entries: (4t)/8 == t/2 (all 4 same).
    const unsigned int* myflag = &g_flag[(tid >> 1) * FSTRIDE];

    const float dt = __ldg(&t[1]) - __ldg(&t[0]);

    float a[32];
#pragma unroll
    for (int i = 0; i < 32; i++) a[i] = __ldg(&A[R * NS + l + 32 * i]);

    float4 xv = *reinterpret_cast<const float4*>(&x0[j0]);
    float xr[4] = {xv.x, xv.y, xv.z, xv.w};
    float k0[4], k1[4], k2[4], k3[4], k4[4], k5[4];

    if ((tid >> 1) == b) *reinterpret_cast<float4*>(&xs[j0]) = xv;

    unsigned sc = 0;   // monotonic stage counter; publish tag = sc after ++

    // tanh -> ty_sm; BAR; matvec; warp reduce; lane0 -> kcol; BAR;
    // thread0 alone: store 8 k values then st.release flag = sc.
    // Single-thread release ordering (no cross-thread fence hole).
#define STAGE_BODY(Y0, Y1, Y2, Y3) do {                                     \
        float4 tv;                                                          \
        tv.x = tanhf(Y0); tv.y = tanhf(Y1);                                 \
        tv.z = tanhf(Y2); tv.w = tanhf(Y3);                                 \
        *reinterpret_cast<float4*>(&ty_sm[j0]) = tv;                        \
        __syncthreads();                                                    \
        float acc0 = 0.f, acc1 = 0.f, acc2 = 0.f, acc3 = 0.f;               \
        _Pragma("unroll")                                                   \
        for (int i = 0; i < 32; i += 4) {                                   \
            acc0 = fmaf(a[i + 0], ty_sm[l + 32 * (i + 0)], acc0);           \
            acc1 = fmaf(a[i + 1], ty_sm[l + 32 * (i + 1)], acc1);           \
            acc2 = fmaf(a[i + 2], ty_sm[l + 32 * (i + 2)], acc2);           \
            acc3 = fmaf(a[i + 3], ty_sm[l + 32 * (i + 3)], acc3);           \
        }                                                                   \
        float acc = (acc0 + acc1) + (acc2 + acc3);                          \
        _Pragma("unroll")                                                   \
        for (int o = 16; o > 0; o >>= 1)                                    \
            acc += __shfl_down_sync(0xffffffffu, acc, o);                   \
        if (l == 0) kcol[w] = acc;                                          \
        __syncthreads();                                                    \
        sc++;                                                               \
        if (tid == 0) {                                                     \
            int S = (int)((sc - 1) % 6u);                                   \
            float4 v0 = *reinterpret_cast<float4*>(&kcol[0]);               \
            float4 v1 = *reinterpret_cast<float4*>(&kcol[4]);               \
            *reinterpret_cast<float4*>(&g_k[S][b * RPB])     = v0;          \
            *reinterpret_cast<float4*>(&g_k[S][b * RPB + 4]) = v1;          \
            asm volatile("st.release.gpu.global.u32 [%0], %1;"              \
                         :: "l"(&g_flag[b * FSTRIDE]), "r"(sc) : "memory"); \
        }                                                                   \
    } while (0)

#define LOADK(KR, S) do {                                                   \
        wait_flag(myflag, sc);                                              \
        float4 kv = __ldcg(reinterpret_cast<const float4*>(&g_k[S][j0]));   \
        KR[0] = kv.x; KR[1] = kv.y; KR[2] = kv.z; KR[3] = kv.w;             \
    } while (0)

    for (int step = 0; step < NT - 1; step++) {
        // stage 1: y = x
        STAGE_BODY(xr[0], xr[1], xr[2], xr[3]);

        // stage 2
        LOADK(k0, 0);
        {
            float y[4];
#pragma unroll
            for (int e = 0; e < 4; e++)
                y[e] = fmaf(dt, 0.2f * k0[e], xr[e]);
            STAGE_BODY(y[0], y[1], y[2], y[3]);
        }

        // stage 3
        LOADK(k1, 1);
        {
            float y[4];
#pragma unroll
            for (int e = 0; e < 4; e++) {
                float acc = (3.0f / 40.0f) * k0[e];
                acc = fmaf(9.0f / 40.0f, k1[e], acc);
                y[e] = fmaf(dt, acc, xr[e]);
            }
            STAGE_BODY(y[0], y[1], y[2], y[3]);
        }

        // stage 4
        LOADK(k2, 2);
        {
            float y[4];
#pragma unroll
            for (int e = 0; e < 4; e++) {
                float acc = (44.0f / 45.0f) * k0[e];
                acc = fmaf(-56.0f / 15.0f, k1[e], acc);
                acc = fmaf(32.0f / 9.0f,  k2[e], acc);
                y[e] = fmaf(dt, acc, xr[e]);
            }
            STAGE_BODY(y[0], y[1], y[2], y[3]);
        }

        // stage 5
        LOADK(k3, 3);
        {
            float y[4];
#pragma unroll
            for (int e = 0; e < 4; e++) {
                float acc = (19372.0f / 6561.0f) * k0[e];
                acc = fmaf(-25360.0f / 2187.0f, k1[e], acc);
                acc = fmaf(64448.0f / 6561.0f,  k2[e], acc);
                acc = fmaf(-212.0f / 729.0f,    k3[e], acc);
                y[e] = fmaf(dt, acc, xr[e]);
            }
            STAGE_BODY(y[0], y[1], y[2], y[3]);
        }

        // stage 6
        LOADK(k4, 4);
        {
            float y[4];
#pragma unroll
            for (int e = 0; e < 4; e++) {
                float acc = (9017.0f / 3168.0f) * k0[e];
                acc = fmaf(-355.0f / 33.0f,     k1[e], acc);
                acc = fmaf(46732.0f / 5247.0f,  k2[e], acc);
                acc = fmaf(49.0f / 176.0f,      k3[e], acc);
                acc = fmaf(-5103.0f / 18656.0f, k4[e], acc);
                y[e] = fmaf(dt, acc, xr[e]);
            }
            STAGE_BODY(y[0], y[1], y[2], y[3]);
        }

        // x update
        LOADK(k5, 5);
#pragma unroll
        for (int e = 0; e < 4; e++) {
            float acc = (35.0f / 384.0f) * k0[e];
            acc = fmaf(500.0f / 1113.0f,   k2[e], acc);
            acc = fmaf(125.0f / 192.0f,    k3[e], acc);
            acc = fmaf(-2187.0f / 6784.0f, k4[e], acc);
            acc = fmaf(11.0f / 84.0f,      k5[e], acc);
            xr[e] = fmaf(dt, acc, xr[e]);
        }
        if ((tid >> 1) == b) {
            float4 o;
            o.x = xr[0]; o.y = xr[1]; o.z = xr[2]; o.w = xr[3];
            *reinterpret_cast<float4*>(&xs[(size_t)(step + 1) * NS + j0]) = o;
        }
    }
#undef STAGE_BODY
#undef LOADK
}

// ---------------------------------------------------------------------------
// ys = xs @ C^T  (8192x1024 @ 1024x256) — 64x64 tiled fp32 GEMM.
// ---------------------------------------------------------------------------
__global__ void __launch_bounds__(256)
gemm_ys(const float* __restrict__ xs, const float* __restrict__ C,
        float* __restrict__ ys)
{
    const int BM = 64, BN = 64, BK = 16;
    __shared__ float As[BK][BM];
    __shared__ float Bs[BK][BN];

    const int tid = threadIdx.x;
    const int m0 = blockIdx.y * BM;
    const int n0 = blockIdx.x * BN;
    const int tx = tid & 15;
    const int ty = tid >> 4;

    const int lr = tid >> 2;
    const int lc = (tid & 3) * 4;

    float acc[4][4];
#pragma unroll
    for (int i = 0; i < 4; i++)
#pragma unroll
        for (int j = 0; j < 4; j++) acc[i][j] = 0.0f;

    for (int kk0 = 0; kk0 < NS; kk0 += BK) {
        float4 av = *reinterpret_cast<const float4*>(
            &xs[(size_t)(m0 + lr) * NS + kk0 + lc]);
        float4 bv = *reinterpret_cast<const float4*>(
            &C[(size_t)(n0 + lr) * NS + kk0 + lc]);
        As[lc + 0][lr] = av.x; As[lc + 1][lr] = av.y;
        As[lc + 2][lr] = av.z; As[lc + 3][lr] = av.w;
        Bs[lc + 0][lr] = bv.x; Bs[lc + 1][lr] = bv.y;
        Bs[lc + 2][lr] = bv.z; Bs[lc + 3][lr] = bv.w;
        __syncthreads();

#pragma unroll
        for (int kk = 0; kk < BK; kk++) {
            float ar[4], br[4];
#pragma unroll
            for (int i = 0; i < 4; i++) ar[i] = As[kk][ty * 4 + i];
#pragma unroll
            for (int j = 0; j < 4; j++) br[j] = Bs[kk][tx * 4 + j];
#pragma unroll
            for (int i = 0; i < 4; i++)
#pragma unroll
                for (int j = 0; j < 4; j++)
                    acc[i][j] = fmaf(ar[i], br[j], acc[i][j]);
        }
        __syncthreads();
    }

#pragma unroll
    for (int i = 0; i < 4; i++)
#pragma unroll
        for (int j = 0; j < 4; j++)
            ys[(size_t)(m0 + ty * 4 + i) * NO + n0 + tx * 4 + j] = acc[i][j];
}

extern "C" void kernel_launch(void* const* d_in, const int* in_sizes, int n_in,
                              void* d_out, int out_size)
{
    const float* x0 = (const float*)d_in[0];
    const float* t  = (const float*)d_in[1];
    const float* A  = (const float*)d_in[2];
    const float* C  = (const float*)d_in[3];
    float* out = (float*)d_out;

    // Reset all per-block flags (graph-replay safe).
    init_kernel<<<16, 256>>>();

    // ODE integration: xs = out[0 : NT*NS]
    ode_kernel<<<NBLK, NTHR>>>(x0, t, A, out);

    // Output projection: ys = out[NT*NS : ]
    dim3 g(NO / 64, NT / 64);
    gemm_ys<<<g, 256>>>(out, C, out + (size_t)NT * NS);
}